// round 13
// baseline (speedup 1.0000x reference)
#include <cuda_runtime.h>
#include <cuda_bf16.h>
#include <math.h>
#include <stdint.h>

#define NODES   661
#define NGRAPH  128
#define NTOT    (NODES * NGRAPH)      // 84608
#define FDIM    64
#define EPG     (NODES * 8)           // 5288 edges per graph per edge set
#define NNZ     (NTOT * 8)            // 676864 per edge set

// ---------------- device scratch (static allocation, allowed) ----------------
__device__ int   g_st4[NTOT * 4];
__device__ int   g_ct4[NTOT * 4];
__device__ int2  g_edge[4 * NNZ];

__device__ float g_e1[NTOT * FDIM];
__device__ float g_f1[NTOT * FDIM];
__device__ float g_e2[NTOT * FDIM];
__device__ float g_f2[NTOT * FDIM];
__device__ float g_e3[NTOT * FDIM];
__device__ float g_f3[NTOT * FDIM];
__device__ float g_ne[NTOT * FDIM];
__device__ float g_nf[NTOT * FDIM];
__device__ float g_att[8 * NGRAPH];

// W split into bf16 hi/lo: [side][64 out][320 in]
__device__ __nv_bfloat16 g_Wh[2 * 64 * 320];
__device__ __nv_bfloat16 g_Wl[2 * 64 * 320];

// ---------------------------------------------------------------------------
// K1: fused CSR build (blocks 0..511) + W bf16 split prep (block 512).
__global__ void __launch_bounds__(1024)
build_csr_kernel(const int* __restrict__ r0, const int* __restrict__ c0, const float* __restrict__ v0,
                 const int* __restrict__ r1, const int* __restrict__ c1, const float* __restrict__ v1,
                 const int* __restrict__ r2, const int* __restrict__ c2, const float* __restrict__ v2,
                 const int* __restrict__ r3, const int* __restrict__ c3, const float* __restrict__ v3,
                 const float* __restrict__ W1, const float* __restrict__ W2) {
    __shared__ int sm[1024];
    __shared__ int scur[NODES];

    const int t = threadIdx.x;

    if (blockIdx.x == 512) {
        for (int i = t; i < 2 * 64 * 320; i += 1024) {
            const float w = (i < 64 * 320) ? W1[i] : W2[i - 64 * 320];
            __nv_bfloat16 h = __float2bfloat16(w);
            __nv_bfloat16 l = __float2bfloat16(w - __bfloat162float(h));
            g_Wh[i] = h;
            g_Wl[i] = l;
        }
        return;
    }

    const int s = blockIdx.x >> 7;
    const int g = blockIdx.x & 127;

    if (blockIdx.x == 0 && t < 8 * NGRAPH) g_att[t] = 0.0f;

    const int*   rw = (s == 0) ? r0 : (s == 1) ? r1 : (s == 2) ? r2 : r3;
    const int*   cw = (s == 0) ? c0 : (s == 1) ? c1 : (s == 2) ? c2 : c3;
    const float* vw = (s == 0) ? v0 : (s == 1) ? v1 : (s == 2) ? v2 : v3;

    const int gbase = g * NODES;
    const int ebase = g * EPG;

    sm[t] = 0;
    __syncthreads();

    for (int i = t; i < EPG; i += 1024) {
        atomicAdd(&sm[rw[ebase + i] - gbase], 1);
    }
    __syncthreads();

    int v = sm[t];
    #pragma unroll
    for (int off = 1; off < 1024; off <<= 1) {
        int add = (t >= off) ? sm[t - off] : 0;
        __syncthreads();
        sm[t] += add;
        __syncthreads();
    }
    if (t < NODES) {
        int start = s * NNZ + ebase + sm[t] - v;
        g_st4[(gbase + t) * 4 + s] = start;
        g_ct4[(gbase + t) * 4 + s] = v;
        scur[t] = start;
    }
    __syncthreads();

    for (int i = t; i < EPG; i += 1024) {
        int   r  = rw[ebase + i] - gbase;
        int   cl = cw[ebase + i] - gbase;
        float vv = vw[ebase + i];
        int p = atomicAdd(&scur[r], 1);
        g_edge[p] = make_int2(cl, __float_as_int(vv));
    }
}

// ---------------------------------------------------------------------------
__device__ __forceinline__ float warp_sum(float v) {
    #pragma unroll
    for (int o = 16; o > 0; o >>= 1) v += __shfl_xor_sync(0xffffffffu, v, o);
    return v;
}

// K2: smem-staged fused SpMM (bit-identical to R12)
__global__ void __launch_bounds__(1024, 1)
spmm_staged_kernel(const float* __restrict__ e, const float* __restrict__ f,
                   const float* __restrict__ Pd, const float* __restrict__ Qd,
                   const float* __restrict__ Gd, const float* __restrict__ Bd,
                   const float* __restrict__ w_ae, const float* __restrict__ w_af) {
    extern __shared__ float2 sEF[];

    const int g     = blockIdx.x >> 1;
    const int half  = blockIdx.x & 1;
    const int tid   = threadIdx.x;
    const int gbase = g * NODES;

    for (int idx = tid; idx < NODES * 8; idx += 1024) {
        int node = idx >> 3, c4 = (idx & 7) * 4;
        const float4 ee = *(const float4*)&e[(gbase + node) * FDIM + half * 32 + c4];
        const float4 ff = *(const float4*)&f[(gbase + node) * FDIM + half * 32 + c4];
        float2* dst = &sEF[node * 32 + c4];
        dst[0] = make_float2(ee.x, ff.x);
        dst[1] = make_float2(ee.y, ff.y);
        dst[2] = make_float2(ee.z, ff.z);
        dst[3] = make_float2(ee.w, ff.w);
    }
    __syncthreads();

    const int warp = tid >> 5;
    const int lane = tid & 31;
    const int feat = half * 32 + lane;

    const float wa = w_ae[feat];
    const float wf = w_af[feat];
    float att[8];
    #pragma unroll
    for (int k = 0; k < 8; k++) att[k] = 0.0f;

    const int4* st4p = (const int4*)g_st4;
    const int4* ct4p = (const int4*)g_ct4;

    int4 st4 = st4p[gbase + warp];
    int4 ct4 = ct4p[gbase + warp];
    int2 nb[4];
    #pragma unroll
    for (int u = 0; u < 4; u++)
        nb[u] = (u < ct4.x) ? g_edge[st4.x + u] : make_int2(0, 0);

    for (int r = warp; r < NODES; r += 32) {
        const int grow = gbase + r;
        int4 st4n, ct4n;

        float res[8];

        #pragma unroll
        for (int s = 0; s < 4; s++) {
            const int st  = (s == 0) ? st4.x : (s == 1) ? st4.y : (s == 2) ? st4.z : st4.w;
            const int len = (s == 0) ? ct4.x : (s == 1) ? ct4.y : (s == 2) ? ct4.z : ct4.w;

            int2 c0 = nb[0], c1 = nb[1], c2 = nb[2], c3 = nb[3];

            int2 d0 = (4 < len) ? g_edge[st + 4] : make_int2(0, 0);
            int2 d1 = (5 < len) ? g_edge[st + 5] : make_int2(0, 0);
            int2 d2 = (6 < len) ? g_edge[st + 6] : make_int2(0, 0);
            int2 d3 = (7 < len) ? g_edge[st + 7] : make_int2(0, 0);

            int stn, lenn;
            if (s < 3) {
                stn  = (s == 0) ? st4.y : (s == 1) ? st4.z : st4.w;
                lenn = (s == 0) ? ct4.y : (s == 1) ? ct4.z : ct4.w;
            } else {
                if (r + 32 < NODES) {
                    st4n = st4p[grow + 32];
                    ct4n = ct4p[grow + 32];
                } else {
                    st4n = st4; ct4n = make_int4(0, 0, 0, 0);
                }
                stn  = st4n.x;
                lenn = ct4n.x;
            }
            #pragma unroll
            for (int u = 0; u < 4; u++)
                nb[u] = (u < lenn) ? g_edge[stn + u] : make_int2(0, 0);

            float sE, sF;
            {
                float2 g0 = sEF[c0.x * 32 + lane];
                float2 g1 = sEF[c1.x * 32 + lane];
                float2 g2 = sEF[c2.x * 32 + lane];
                float2 g3 = sEF[c3.x * 32 + lane];
                float v0 = __int_as_float(c0.y), v1 = __int_as_float(c1.y);
                float v2 = __int_as_float(c2.y), v3 = __int_as_float(c3.y);
                sE = v0 * g0.x + v1 * g1.x + v2 * g2.x + v3 * g3.x;
                sF = v0 * g0.y + v1 * g1.y + v2 * g2.y + v3 * g3.y;
            }
            {
                float2 g0 = sEF[d0.x * 32 + lane];
                float2 g1 = sEF[d1.x * 32 + lane];
                float2 g2 = sEF[d2.x * 32 + lane];
                float2 g3 = sEF[d3.x * 32 + lane];
                float v0 = __int_as_float(d0.y), v1 = __int_as_float(d1.y);
                float v2 = __int_as_float(d2.y), v3 = __int_as_float(d3.y);
                sE += v0 * g0.x + v1 * g1.x + v2 * g2.x + v3 * g3.x;
                sF += v0 * g0.y + v1 * g1.y + v2 * g2.y + v3 * g3.y;
            }
            for (int j0 = 8; j0 < len; j0 += 4) {
                int2 t0 = (j0     < len) ? g_edge[st + j0]     : make_int2(0, 0);
                int2 t1 = (j0 + 1 < len) ? g_edge[st + j0 + 1] : make_int2(0, 0);
                int2 t2 = (j0 + 2 < len) ? g_edge[st + j0 + 2] : make_int2(0, 0);
                int2 t3 = (j0 + 3 < len) ? g_edge[st + j0 + 3] : make_int2(0, 0);
                float2 g0 = sEF[t0.x * 32 + lane];
                float2 g1 = sEF[t1.x * 32 + lane];
                float2 g2 = sEF[t2.x * 32 + lane];
                float2 g3 = sEF[t3.x * 32 + lane];
                float v0 = __int_as_float(t0.y), v1 = __int_as_float(t1.y);
                float v2 = __int_as_float(t2.y), v3 = __int_as_float(t3.y);
                sE += v0 * g0.x + v1 * g1.x + v2 * g2.x + v3 * g3.x;
                sF += v0 * g0.y + v1 * g1.y + v2 * g2.y + v3 * g3.y;
            }

            res[2 * s]     = sE;
            res[2 * s + 1] = sF;
        }

        st4 = st4n;
        ct4 = ct4n;

        const float eG = res[0], fG = res[1], eB = res[2], fB = res[3];
        const float e1v = res[4], f1v = res[5], e2v = res[6], f2v = res[7];

        float2 evfv = sEF[r * 32 + lane];
        const float ev = evfv.x, fv = evfv.y;
        const float P = Pd[grow], Q = Qd[grow];
        const float G = Gd[grow], B = Bd[grow];

        const float v2   = ev * ev + fv * fv;
        const float invb = 1.0f / (v2 + 0.1f);
        const float alpha = (P * ev + Q * fv) * invb - eG - fB;
        const float beta  = (Q * ev - P * fv) * invb + fG + eB;
        const float invgb = 1.0f / (G * G + B * B);
        const float e3 = (alpha * G + beta * B) * invgb;
        const float f3 = (beta * G - alpha * B) * invgb;

        const float b1 = eG - fB;
        const float b2 = fG + eB;
        const float P_ = P - v2 * G;
        const float Q_ = Q + v2 * B;
        const float ne = (P_ * b1 + Q_ * b2) * invgb;
        const float nf = (P_ * b2 - Q_ * b1) * invgb;

        const int oi = grow * FDIM + feat;
        g_e3[oi] = e3;  g_f3[oi] = f3;
        g_ne[oi] = ne;  g_nf[oi] = nf;
        g_e1[oi] = e1v; g_f1[oi] = f1v;
        g_e2[oi] = e2v; g_f2[oi] = f2v;

        att[0] += wa * e3;  att[1] += wa * ne;  att[2] += wa * e1v; att[3] += wa * e2v;
        att[4] += wf * f3;  att[5] += wf * nf;  att[6] += wf * f1v; att[7] += wf * f2v;
    }

    float c0 = warp_sum(att[0]);
    float c1 = warp_sum(att[1]);
    float c2 = warp_sum(att[2]);
    float c3 = warp_sum(att[3]);
    float c4 = warp_sum(att[4]);
    float c5 = warp_sum(att[5]);
    float c6 = warp_sum(att[6]);
    float c7 = warp_sum(att[7]);

    float sel = 0.0f;
    if      (lane == 0) sel = c0;
    else if (lane == 1) sel = c1;
    else if (lane == 2) sel = c2;
    else if (lane == 3) sel = c3;
    else if (lane == 4) sel = c4;
    else if (lane == 5) sel = c5;
    else if (lane == 6) sel = c6;
    else if (lane == 7) sel = c7;
    if (lane < 8) atomicAdd(&g_att[lane * NGRAPH + g], sel);
}

// ---------------------------------------------------------------------------
// K3: mma.sync bf16 split-precision GEMM + tanh (bit-identical to R12).
__device__ __forceinline__ float tanh_approx(float x) {
    float y;
    asm("tanh.approx.f32 %0, %1;" : "=f"(y) : "f"(x));
    return y;
}
__device__ __forceinline__ void split2(float x, float y, uint32_t& h, uint32_t& l) {
    __nv_bfloat16 hx = __float2bfloat16(x), hy = __float2bfloat16(y);
    float rx = x - __bfloat162float(hx);
    float ry = y - __bfloat162float(hy);
    __nv_bfloat16 lx = __float2bfloat16(rx), ly = __float2bfloat16(ry);
    h = ((uint32_t)__bfloat16_as_ushort(hy) << 16) | (uint32_t)__bfloat16_as_ushort(hx);
    l = ((uint32_t)__bfloat16_as_ushort(ly) << 16) | (uint32_t)__bfloat16_as_ushort(lx);
}
__device__ __forceinline__ void mma16816(float* d, const uint32_t* a, const uint32_t* b) {
    asm volatile(
        "mma.sync.aligned.m16n8k16.row.col.f32.bf16.bf16.f32 "
        "{%0,%1,%2,%3}, {%4,%5,%6,%7}, {%8,%9}, {%0,%1,%2,%3};\n"
        : "+f"(d[0]), "+f"(d[1]), "+f"(d[2]), "+f"(d[3])
        : "r"(a[0]), "r"(a[1]), "r"(a[2]), "r"(a[3]), "r"(b[0]), "r"(b[1]));
}

#define BPITCH 328
#define GM_SMEM (2 * 64 * BPITCH * 2 + (5 * 128 + 64) * 4)

__global__ void __launch_bounds__(128)
gemm_mma_kernel(const float* __restrict__ e, const float* __restrict__ f,
                const float* __restrict__ bv1, const float* __restrict__ bv2,
                const float* __restrict__ b_ae, const float* __restrict__ b_af,
                float* __restrict__ out) {
    extern __shared__ char dsm[];
    __nv_bfloat16* sBh = (__nv_bfloat16*)dsm;            // [64][BPITCH]
    __nv_bfloat16* sBl = sBh + 64 * BPITCH;
    float* s_att  = (float*)(sBl + 64 * BPITCH);          // [5][128]
    float* s_bias = s_att + 5 * 128;                      // [64]

    const int tid  = threadIdx.x;
    const int wid  = tid >> 5;
    const int lane = tid & 31;
    const int tile = blockIdx.x;
    const int side = blockIdx.y;

    {
        const uint32_t* wh = (const uint32_t*)g_Wh + side * 10240;
        const uint32_t* wl = (const uint32_t*)g_Wl + side * 10240;
        uint32_t* dh = (uint32_t*)sBh;
        uint32_t* dl = (uint32_t*)sBl;
        for (int i = tid; i < 10240; i += 128) {
            int j = i / 160;
            int w = i - j * 160;
            dh[j * (BPITCH / 2) + w] = wh[i];
            dl[j * (BPITCH / 2) + w] = wl[i];
        }
    }
    const float* bv = side ? bv2 : bv1;
    if (tid < 64) s_bias[tid] = bv[tid];

    {
        const int grow = tile * 128 + tid;
        const int gph  = grow / NODES;
        float bias = side ? b_af[0] : b_ae[0];
        float ssum = 1e-4f;
        float av[4];
        #pragma unroll
        for (int k = 0; k < 4; k++) {
            float sc = g_att[(side * 4 + k) * NGRAPH + gph] * (1.0f / (float)NODES) + bias;
            float sg = 1.0f / (1.0f + expf(-sc));
            av[k] = sg;
            ssum += sg;
        }
        float inv = 1.0f / ssum;
        #pragma unroll
        for (int k = 0; k < 4; k++) s_att[k * 128 + tid] = av[k] * inv;
        s_att[4 * 128 + tid] = 1.0f;
    }
    __syncthreads();

    float acc[2][8][4];
    #pragma unroll
    for (int mt = 0; mt < 2; mt++)
        #pragma unroll
        for (int nt = 0; nt < 8; nt++)
            #pragma unroll
            for (int q = 0; q < 4; q++) acc[mt][nt][q] = 0.0f;

    const int rquad = lane >> 2;
    const int kpair = (lane & 3) * 2;

    #pragma unroll 1
    for (int s = 0; s < 5; s++) {
        const float* src;
        if (side == 0) {
            switch (s) {
                case 0: src = g_e3; break;
                case 1: src = g_ne; break;
                case 2: src = g_e1; break;
                case 3: src = g_e2; break;
                default: src = e;   break;
            }
        } else {
            switch (s) {
                case 0: src = g_f3; break;
                case 1: src = g_nf; break;
                case 2: src = g_f1; break;
                case 3: src = g_f2; break;
                default: src = f;   break;
            }
        }
        src += (size_t)(tile * 128) * FDIM;

        float attr[4];
        #pragma unroll
        for (int q = 0; q < 4; q++)
            attr[q] = s_att[s * 128 + wid * 32 + q * 8 + rquad];

        #pragma unroll
        for (int kk = 0; kk < 4; kk++) {
            const int kb = kk * 16;

            uint32_t Ah[2][4], Al[2][4];
            #pragma unroll
            for (int mt = 0; mt < 2; mt++) {
                const int lr = wid * 32 + mt * 16 + rquad;
                const float* p0 = src + lr * FDIM + kb + kpair;
                float2 v00 = *(const float2*)(p0);
                float2 v10 = *(const float2*)(p0 + 8 * FDIM);
                float2 v01 = *(const float2*)(p0 + 8);
                float2 v11 = *(const float2*)(p0 + 8 * FDIM + 8);
                const float a0 = attr[mt * 2];
                const float a1 = attr[mt * 2 + 1];
                split2(v00.x * a0, v00.y * a0, Ah[mt][0], Al[mt][0]);
                split2(v10.x * a1, v10.y * a1, Ah[mt][1], Al[mt][1]);
                split2(v01.x * a0, v01.y * a0, Ah[mt][2], Al[mt][2]);
                split2(v11.x * a1, v11.y * a1, Ah[mt][3], Al[mt][3]);
            }

            uint32_t Bh[8][2], Bl[8][2];
            const int kc = s * 64 + kb + kpair;
            #pragma unroll
            for (int nt = 0; nt < 8; nt++) {
                const int n = nt * 8 + rquad;
                Bh[nt][0] = *(const uint32_t*)&sBh[n * BPITCH + kc];
                Bh[nt][1] = *(const uint32_t*)&sBh[n * BPITCH + kc + 8];
                Bl[nt][0] = *(const uint32_t*)&sBl[n * BPITCH + kc];
                Bl[nt][1] = *(const uint32_t*)&sBl[n * BPITCH + kc + 8];
            }

            #pragma unroll
            for (int mt = 0; mt < 2; mt++) {
                #pragma unroll
                for (int nt = 0; nt < 8; nt++) {
                    mma16816(acc[mt][nt], Ah[mt], Bh[nt]);
                    mma16816(acc[mt][nt], Al[mt], Bh[nt]);
                    mma16816(acc[mt][nt], Ah[mt], Bl[nt]);
                }
            }
        }
    }

    #pragma unroll
    for (int mt = 0; mt < 2; mt++) {
        const int lr = wid * 32 + mt * 16 + rquad;
        float* op0 = out + (size_t)side * NTOT * FDIM + (size_t)(tile * 128 + lr) * FDIM;
        float* op1 = op0 + 8 * FDIM;
        #pragma unroll
        for (int nt = 0; nt < 8; nt++) {
            const int c = nt * 8 + kpair;
            float2 v0, v1;
            v0.x = tanh_approx(acc[mt][nt][0] + s_bias[c]);
            v0.y = tanh_approx(acc[mt][nt][1] + s_bias[c + 1]);
            v1.x = tanh_approx(acc[mt][nt][2] + s_bias[c]);
            v1.y = tanh_approx(acc[mt][nt][3] + s_bias[c + 1]);
            *(float2*)(op0 + c) = v0;
            *(float2*)(op1 + c) = v1;
        }
    }
}

// ---------------------------------------------------------------------------
extern "C" void kernel_launch(void* const* d_in, const int* in_sizes, int n_in,
                              void* d_out, int out_size) {
    const float* e     = (const float*)d_in[0];
    const float* f     = (const float*)d_in[1];
    const int*   rowsG = (const int*)d_in[2];
    const int*   colsG = (const int*)d_in[3];
    const float* valsG = (const float*)d_in[4];
    const int*   rowsB = (const int*)d_in[5];
    const int*   colsB = (const int*)d_in[6];
    const float* valsB = (const float*)d_in[7];
    const int*   rows1 = (const int*)d_in[8];
    const int*   cols1 = (const int*)d_in[9];
    const float* vals1 = (const float*)d_in[10];
    const int*   rows2 = (const int*)d_in[11];
    const int*   cols2 = (const int*)d_in[12];
    const float* vals2 = (const float*)d_in[13];
    const float* G_diag = (const float*)d_in[14];
    const float* B_diag = (const float*)d_in[15];
    const float* Pd    = (const float*)d_in[16];
    const float* Qd    = (const float*)d_in[17];
    const float* W_v1  = (const float*)d_in[18];
    const float* b_v1  = (const float*)d_in[19];
    const float* W_v2  = (const float*)d_in[20];
    const float* b_v2  = (const float*)d_in[21];
    const float* w_ae  = (const float*)d_in[22];
    const float* b_ae  = (const float*)d_in[23];
    const float* w_af  = (const float*)d_in[24];
    const float* b_af  = (const float*)d_in[25];
    float* out = (float*)d_out;

    const int spmm_smem = NODES * 32 * (int)sizeof(float2);   // 169216

    cudaFuncSetAttribute(spmm_staged_kernel, cudaFuncAttributeMaxDynamicSharedMemorySize, spmm_smem);
    cudaFuncSetAttribute(gemm_mma_kernel, cudaFuncAttributeMaxDynamicSharedMemorySize, GM_SMEM);

    build_csr_kernel<<<513, 1024>>>(rowsG, colsG, valsG,
                                    rowsB, colsB, valsB,
                                    rows1, cols1, vals1,
                                    rows2, cols2, vals2,
                                    W_v1, W_v2);

    spmm_staged_kernel<<<NGRAPH * 2, 1024, spmm_smem>>>(e, f, Pd, Qd, G_diag, B_diag, w_ae, w_af);

    dim3 ggrid(NTOT / 128, 2);
    // MEASUREMENT: gemm launched twice (idempotent, writes identical output).
    // dur_us - 313.9 = gemm time; isolates the spmm/gemm split for round 14.
    gemm_mma_kernel<<<ggrid, 128, GM_SMEM>>>(e, f, b_v1, b_v2, b_ae, b_af, out);
    gemm_mma_kernel<<<ggrid, 128, GM_SMEM>>>(e, f, b_v1, b_v2, b_ae, b_af, out);
}

// round 14
// speedup vs baseline: 1.4857x; 1.4857x over previous
#include <cuda_runtime.h>
#include <cuda_bf16.h>
#include <math.h>
#include <stdint.h>

#define NODES   661
#define NGRAPH  128
#define NTOT    (NODES * NGRAPH)      // 84608
#define FDIM    64
#define EPG     (NODES * 8)           // 5288 edges per graph per edge set
#define NNZ     (NTOT * 8)            // 676864 per edge set

// ---------------- device scratch (static allocation, allowed) ----------------
__device__ int   g_st4[NTOT * 4];
__device__ int   g_ct4[NTOT * 4];
__device__ int2  g_edge[4 * NNZ];

__device__ float g_e1[NTOT * FDIM];
__device__ float g_f1[NTOT * FDIM];
__device__ float g_e2[NTOT * FDIM];
__device__ float g_f2[NTOT * FDIM];
__device__ float g_e3[NTOT * FDIM];
__device__ float g_f3[NTOT * FDIM];
__device__ float g_ne[NTOT * FDIM];
__device__ float g_nf[NTOT * FDIM];
__device__ float g_att[8 * NGRAPH];

// W split into bf16 hi/lo: [side][64 out][320 in]
__device__ __nv_bfloat16 g_Wh[2 * 64 * 320];
__device__ __nv_bfloat16 g_Wl[2 * 64 * 320];

// ---------------------------------------------------------------------------
// K1: fused CSR build (blocks 0..511) + W bf16 split prep (block 512).
__global__ void __launch_bounds__(1024)
build_csr_kernel(const int* __restrict__ r0, const int* __restrict__ c0, const float* __restrict__ v0,
                 const int* __restrict__ r1, const int* __restrict__ c1, const float* __restrict__ v1,
                 const int* __restrict__ r2, const int* __restrict__ c2, const float* __restrict__ v2,
                 const int* __restrict__ r3, const int* __restrict__ c3, const float* __restrict__ v3,
                 const float* __restrict__ W1, const float* __restrict__ W2) {
    __shared__ int sm[1024];
    __shared__ int scur[NODES];

    const int t = threadIdx.x;

    if (blockIdx.x == 512) {
        for (int i = t; i < 2 * 64 * 320; i += 1024) {
            const float w = (i < 64 * 320) ? W1[i] : W2[i - 64 * 320];
            __nv_bfloat16 h = __float2bfloat16(w);
            __nv_bfloat16 l = __float2bfloat16(w - __bfloat162float(h));
            g_Wh[i] = h;
            g_Wl[i] = l;
        }
        return;
    }

    const int s = blockIdx.x >> 7;
    const int g = blockIdx.x & 127;

    if (blockIdx.x == 0 && t < 8 * NGRAPH) g_att[t] = 0.0f;

    const int*   rw = (s == 0) ? r0 : (s == 1) ? r1 : (s == 2) ? r2 : r3;
    const int*   cw = (s == 0) ? c0 : (s == 1) ? c1 : (s == 2) ? c2 : c3;
    const float* vw = (s == 0) ? v0 : (s == 1) ? v1 : (s == 2) ? v2 : v3;

    const int gbase = g * NODES;
    const int ebase = g * EPG;

    sm[t] = 0;
    __syncthreads();

    for (int i = t; i < EPG; i += 1024) {
        atomicAdd(&sm[rw[ebase + i] - gbase], 1);
    }
    __syncthreads();

    int v = sm[t];
    #pragma unroll
    for (int off = 1; off < 1024; off <<= 1) {
        int add = (t >= off) ? sm[t - off] : 0;
        __syncthreads();
        sm[t] += add;
        __syncthreads();
    }
    if (t < NODES) {
        int start = s * NNZ + ebase + sm[t] - v;
        g_st4[(gbase + t) * 4 + s] = start;
        g_ct4[(gbase + t) * 4 + s] = v;
        scur[t] = start;
    }
    __syncthreads();

    for (int i = t; i < EPG; i += 1024) {
        int   r  = rw[ebase + i] - gbase;
        int   cl = cw[ebase + i] - gbase;
        float vv = vw[ebase + i];
        int p = atomicAdd(&scur[r], 1);
        g_edge[p] = make_int2(cl, __float_as_int(vv));
    }
}

// ---------------------------------------------------------------------------
__device__ __forceinline__ float warp_sum(float v) {
    #pragma unroll
    for (int o = 16; o > 0; o >>= 1) v += __shfl_xor_sync(0xffffffffu, v, o);
    return v;
}

// K2: smem-staged fused SpMM (bit-identical to R12)
__global__ void __launch_bounds__(1024, 1)
spmm_staged_kernel(const float* __restrict__ e, const float* __restrict__ f,
                   const float* __restrict__ Pd, const float* __restrict__ Qd,
                   const float* __restrict__ Gd, const float* __restrict__ Bd,
                   const float* __restrict__ w_ae, const float* __restrict__ w_af) {
    extern __shared__ float2 sEF[];

    const int g     = blockIdx.x >> 1;
    const int half  = blockIdx.x & 1;
    const int tid   = threadIdx.x;
    const int gbase = g * NODES;

    for (int idx = tid; idx < NODES * 8; idx += 1024) {
        int node = idx >> 3, c4 = (idx & 7) * 4;
        const float4 ee = *(const float4*)&e[(gbase + node) * FDIM + half * 32 + c4];
        const float4 ff = *(const float4*)&f[(gbase + node) * FDIM + half * 32 + c4];
        float2* dst = &sEF[node * 32 + c4];
        dst[0] = make_float2(ee.x, ff.x);
        dst[1] = make_float2(ee.y, ff.y);
        dst[2] = make_float2(ee.z, ff.z);
        dst[3] = make_float2(ee.w, ff.w);
    }
    __syncthreads();

    const int warp = tid >> 5;
    const int lane = tid & 31;
    const int feat = half * 32 + lane;

    const float wa = w_ae[feat];
    const float wf = w_af[feat];
    float att[8];
    #pragma unroll
    for (int k = 0; k < 8; k++) att[k] = 0.0f;

    const int4* st4p = (const int4*)g_st4;
    const int4* ct4p = (const int4*)g_ct4;

    int4 st4 = st4p[gbase + warp];
    int4 ct4 = ct4p[gbase + warp];
    int2 nb[4];
    #pragma unroll
    for (int u = 0; u < 4; u++)
        nb[u] = (u < ct4.x) ? g_edge[st4.x + u] : make_int2(0, 0);

    for (int r = warp; r < NODES; r += 32) {
        const int grow = gbase + r;
        int4 st4n, ct4n;

        float res[8];

        #pragma unroll
        for (int s = 0; s < 4; s++) {
            const int st  = (s == 0) ? st4.x : (s == 1) ? st4.y : (s == 2) ? st4.z : st4.w;
            const int len = (s == 0) ? ct4.x : (s == 1) ? ct4.y : (s == 2) ? ct4.z : ct4.w;

            int2 c0 = nb[0], c1 = nb[1], c2 = nb[2], c3 = nb[3];

            int2 d0 = (4 < len) ? g_edge[st + 4] : make_int2(0, 0);
            int2 d1 = (5 < len) ? g_edge[st + 5] : make_int2(0, 0);
            int2 d2 = (6 < len) ? g_edge[st + 6] : make_int2(0, 0);
            int2 d3 = (7 < len) ? g_edge[st + 7] : make_int2(0, 0);

            int stn, lenn;
            if (s < 3) {
                stn  = (s == 0) ? st4.y : (s == 1) ? st4.z : st4.w;
                lenn = (s == 0) ? ct4.y : (s == 1) ? ct4.z : ct4.w;
            } else {
                if (r + 32 < NODES) {
                    st4n = st4p[grow + 32];
                    ct4n = ct4p[grow + 32];
                } else {
                    st4n = st4; ct4n = make_int4(0, 0, 0, 0);
                }
                stn  = st4n.x;
                lenn = ct4n.x;
            }
            #pragma unroll
            for (int u = 0; u < 4; u++)
                nb[u] = (u < lenn) ? g_edge[stn + u] : make_int2(0, 0);

            float sE, sF;
            {
                float2 g0 = sEF[c0.x * 32 + lane];
                float2 g1 = sEF[c1.x * 32 + lane];
                float2 g2 = sEF[c2.x * 32 + lane];
                float2 g3 = sEF[c3.x * 32 + lane];
                float v0 = __int_as_float(c0.y), v1 = __int_as_float(c1.y);
                float v2 = __int_as_float(c2.y), v3 = __int_as_float(c3.y);
                sE = v0 * g0.x + v1 * g1.x + v2 * g2.x + v3 * g3.x;
                sF = v0 * g0.y + v1 * g1.y + v2 * g2.y + v3 * g3.y;
            }
            {
                float2 g0 = sEF[d0.x * 32 + lane];
                float2 g1 = sEF[d1.x * 32 + lane];
                float2 g2 = sEF[d2.x * 32 + lane];
                float2 g3 = sEF[d3.x * 32 + lane];
                float v0 = __int_as_float(d0.y), v1 = __int_as_float(d1.y);
                float v2 = __int_as_float(d2.y), v3 = __int_as_float(d3.y);
                sE += v0 * g0.x + v1 * g1.x + v2 * g2.x + v3 * g3.x;
                sF += v0 * g0.y + v1 * g1.y + v2 * g2.y + v3 * g3.y;
            }
            for (int j0 = 8; j0 < len; j0 += 4) {
                int2 t0 = (j0     < len) ? g_edge[st + j0]     : make_int2(0, 0);
                int2 t1 = (j0 + 1 < len) ? g_edge[st + j0 + 1] : make_int2(0, 0);
                int2 t2 = (j0 + 2 < len) ? g_edge[st + j0 + 2] : make_int2(0, 0);
                int2 t3 = (j0 + 3 < len) ? g_edge[st + j0 + 3] : make_int2(0, 0);
                float2 g0 = sEF[t0.x * 32 + lane];
                float2 g1 = sEF[t1.x * 32 + lane];
                float2 g2 = sEF[t2.x * 32 + lane];
                float2 g3 = sEF[t3.x * 32 + lane];
                float v0 = __int_as_float(t0.y), v1 = __int_as_float(t1.y);
                float v2 = __int_as_float(t2.y), v3 = __int_as_float(t3.y);
                sE += v0 * g0.x + v1 * g1.x + v2 * g2.x + v3 * g3.x;
                sF += v0 * g0.y + v1 * g1.y + v2 * g2.y + v3 * g3.y;
            }

            res[2 * s]     = sE;
            res[2 * s + 1] = sF;
        }

        st4 = st4n;
        ct4 = ct4n;

        const float eG = res[0], fG = res[1], eB = res[2], fB = res[3];
        const float e1v = res[4], f1v = res[5], e2v = res[6], f2v = res[7];

        float2 evfv = sEF[r * 32 + lane];
        const float ev = evfv.x, fv = evfv.y;
        const float P = Pd[grow], Q = Qd[grow];
        const float G = Gd[grow], B = Bd[grow];

        const float v2   = ev * ev + fv * fv;
        const float invb = 1.0f / (v2 + 0.1f);
        const float alpha = (P * ev + Q * fv) * invb - eG - fB;
        const float beta  = (Q * ev - P * fv) * invb + fG + eB;
        const float invgb = 1.0f / (G * G + B * B);
        const float e3 = (alpha * G + beta * B) * invgb;
        const float f3 = (beta * G - alpha * B) * invgb;

        const float b1 = eG - fB;
        const float b2 = fG + eB;
        const float P_ = P - v2 * G;
        const float Q_ = Q + v2 * B;
        const float ne = (P_ * b1 + Q_ * b2) * invgb;
        const float nf = (P_ * b2 - Q_ * b1) * invgb;

        const int oi = grow * FDIM + feat;
        g_e3[oi] = e3;  g_f3[oi] = f3;
        g_ne[oi] = ne;  g_nf[oi] = nf;
        g_e1[oi] = e1v; g_f1[oi] = f1v;
        g_e2[oi] = e2v; g_f2[oi] = f2v;

        att[0] += wa * e3;  att[1] += wa * ne;  att[2] += wa * e1v; att[3] += wa * e2v;
        att[4] += wf * f3;  att[5] += wf * nf;  att[6] += wf * f1v; att[7] += wf * f2v;
    }

    float c0 = warp_sum(att[0]);
    float c1 = warp_sum(att[1]);
    float c2 = warp_sum(att[2]);
    float c3 = warp_sum(att[3]);
    float c4 = warp_sum(att[4]);
    float c5 = warp_sum(att[5]);
    float c6 = warp_sum(att[6]);
    float c7 = warp_sum(att[7]);

    float sel = 0.0f;
    if      (lane == 0) sel = c0;
    else if (lane == 1) sel = c1;
    else if (lane == 2) sel = c2;
    else if (lane == 3) sel = c3;
    else if (lane == 4) sel = c4;
    else if (lane == 5) sel = c5;
    else if (lane == 6) sel = c6;
    else if (lane == 7) sel = c7;
    if (lane < 8) atomicAdd(&g_att[lane * NGRAPH + g], sel);
}

// ---------------------------------------------------------------------------
// K3: mma.sync bf16 split-precision GEMM + tanh.
// NOW 256 threads / 8 warps per CTA; warp = 16 rows x 64 cols (1 m-tile, 8 n-tiles).
// Same 128-row CTA tile and smem -> 2 CTAs/SM but 16 warps/SM (2x occupancy).
__device__ __forceinline__ float tanh_approx(float x) {
    float y;
    asm("tanh.approx.f32 %0, %1;" : "=f"(y) : "f"(x));
    return y;
}
__device__ __forceinline__ void split2(float x, float y, uint32_t& h, uint32_t& l) {
    __nv_bfloat16 hx = __float2bfloat16(x), hy = __float2bfloat16(y);
    float rx = x - __bfloat162float(hx);
    float ry = y - __bfloat162float(hy);
    __nv_bfloat16 lx = __float2bfloat16(rx), ly = __float2bfloat16(ry);
    h = ((uint32_t)__bfloat16_as_ushort(hy) << 16) | (uint32_t)__bfloat16_as_ushort(hx);
    l = ((uint32_t)__bfloat16_as_ushort(ly) << 16) | (uint32_t)__bfloat16_as_ushort(lx);
}
__device__ __forceinline__ void mma16816(float* d, const uint32_t* a, const uint32_t* b) {
    asm volatile(
        "mma.sync.aligned.m16n8k16.row.col.f32.bf16.bf16.f32 "
        "{%0,%1,%2,%3}, {%4,%5,%6,%7}, {%8,%9}, {%0,%1,%2,%3};\n"
        : "+f"(d[0]), "+f"(d[1]), "+f"(d[2]), "+f"(d[3])
        : "r"(a[0]), "r"(a[1]), "r"(a[2]), "r"(a[3]), "r"(b[0]), "r"(b[1]));
}

#define BPITCH 328
#define GM_SMEM (2 * 64 * BPITCH * 2 + (5 * 128 + 64) * 4)

__global__ void __launch_bounds__(256)
gemm_mma_kernel(const float* __restrict__ e, const float* __restrict__ f,
                const float* __restrict__ bv1, const float* __restrict__ bv2,
                const float* __restrict__ b_ae, const float* __restrict__ b_af,
                float* __restrict__ out) {
    extern __shared__ char dsm[];
    __nv_bfloat16* sBh = (__nv_bfloat16*)dsm;            // [64][BPITCH]
    __nv_bfloat16* sBl = sBh + 64 * BPITCH;
    float* s_att  = (float*)(sBl + 64 * BPITCH);          // [5][128]
    float* s_bias = s_att + 5 * 128;                      // [64]

    const int tid  = threadIdx.x;
    const int wid  = tid >> 5;       // 0..7
    const int lane = tid & 31;
    const int tile = blockIdx.x;     // 0..660
    const int side = blockIdx.y;

    // stage W^T hi/lo into padded smem
    {
        const uint32_t* wh = (const uint32_t*)g_Wh + side * 10240;
        const uint32_t* wl = (const uint32_t*)g_Wl + side * 10240;
        uint32_t* dh = (uint32_t*)sBh;
        uint32_t* dl = (uint32_t*)sBl;
        for (int i = tid; i < 10240; i += 256) {
            int j = i / 160;
            int w = i - j * 160;
            dh[j * (BPITCH / 2) + w] = wh[i];
            dl[j * (BPITCH / 2) + w] = wl[i];
        }
    }
    const float* bv = side ? bv2 : bv1;
    if (tid < 64) s_bias[tid] = bv[tid];

    // per-row attention coefficients (rows 0..127 of this tile)
    if (tid < 128) {
        const int grow = tile * 128 + tid;
        const int gph  = grow / NODES;
        float bias = side ? b_af[0] : b_ae[0];
        float ssum = 1e-4f;
        float av[4];
        #pragma unroll
        for (int k = 0; k < 4; k++) {
            float sc = g_att[(side * 4 + k) * NGRAPH + gph] * (1.0f / (float)NODES) + bias;
            float sg = 1.0f / (1.0f + expf(-sc));
            av[k] = sg;
            ssum += sg;
        }
        float inv = 1.0f / ssum;
        #pragma unroll
        for (int k = 0; k < 4; k++) s_att[k * 128 + tid] = av[k] * inv;
        s_att[4 * 128 + tid] = 1.0f;
    }
    __syncthreads();

    float acc[8][4];
    #pragma unroll
    for (int nt = 0; nt < 8; nt++)
        #pragma unroll
        for (int q = 0; q < 4; q++) acc[nt][q] = 0.0f;

    const int rquad = lane >> 2;      // 0..7
    const int kpair = (lane & 3) * 2; // 0,2,4,6
    const int lr0   = wid * 16 + rquad;   // this warp's m-tile rows: lr0 and lr0+8

    #pragma unroll 1
    for (int s = 0; s < 5; s++) {
        const float* src;
        if (side == 0) {
            switch (s) {
                case 0: src = g_e3; break;
                case 1: src = g_ne; break;
                case 2: src = g_e1; break;
                case 3: src = g_e2; break;
                default: src = e;   break;
            }
        } else {
            switch (s) {
                case 0: src = g_f3; break;
                case 1: src = g_nf; break;
                case 2: src = g_f1; break;
                case 3: src = g_f2; break;
                default: src = f;   break;
            }
        }
        src += (size_t)(tile * 128) * FDIM;

        const float a0 = s_att[s * 128 + lr0];
        const float a1 = s_att[s * 128 + lr0 + 8];

        #pragma unroll
        for (int kk = 0; kk < 4; kk++) {
            const int kb = kk * 16;

            // A fragment (1 m-tile), att-scaled, split hi/lo
            uint32_t Ah[4], Al[4];
            {
                const float* p0 = src + lr0 * FDIM + kb + kpair;
                float2 v00 = *(const float2*)(p0);
                float2 v10 = *(const float2*)(p0 + 8 * FDIM);
                float2 v01 = *(const float2*)(p0 + 8);
                float2 v11 = *(const float2*)(p0 + 8 * FDIM + 8);
                split2(v00.x * a0, v00.y * a0, Ah[0], Al[0]);
                split2(v10.x * a1, v10.y * a1, Ah[1], Al[1]);
                split2(v01.x * a0, v01.y * a0, Ah[2], Al[2]);
                split2(v11.x * a1, v11.y * a1, Ah[3], Al[3]);
            }

            // B fragments (8 n-tiles) hi/lo from smem
            uint32_t Bh[8][2], Bl[8][2];
            const int kc = s * 64 + kb + kpair;
            #pragma unroll
            for (int nt = 0; nt < 8; nt++) {
                const int n = nt * 8 + rquad;
                Bh[nt][0] = *(const uint32_t*)&sBh[n * BPITCH + kc];
                Bh[nt][1] = *(const uint32_t*)&sBh[n * BPITCH + kc + 8];
                Bl[nt][0] = *(const uint32_t*)&sBl[n * BPITCH + kc];
                Bl[nt][1] = *(const uint32_t*)&sBl[n * BPITCH + kc + 8];
            }

            #pragma unroll
            for (int nt = 0; nt < 8; nt++) {
                mma16816(acc[nt], Ah, Bh[nt]);
                mma16816(acc[nt], Al, Bh[nt]);
                mma16816(acc[nt], Ah, Bl[nt]);
            }
        }
    }

    // epilogue: bias + tanh + store (rows lr0 and lr0+8)
    {
        float* op0 = out + (size_t)side * NTOT * FDIM + (size_t)(tile * 128 + lr0) * FDIM;
        float* op1 = op0 + 8 * FDIM;
        #pragma unroll
        for (int nt = 0; nt < 8; nt++) {
            const int c = nt * 8 + kpair;
            float2 v0, v1;
            v0.x = tanh_approx(acc[nt][0] + s_bias[c]);
            v0.y = tanh_approx(acc[nt][1] + s_bias[c + 1]);
            v1.x = tanh_approx(acc[nt][2] + s_bias[c]);
            v1.y = tanh_approx(acc[nt][3] + s_bias[c + 1]);
            *(float2*)(op0 + c) = v0;
            *(float2*)(op1 + c) = v1;
        }
    }
}

// ---------------------------------------------------------------------------
extern "C" void kernel_launch(void* const* d_in, const int* in_sizes, int n_in,
                              void* d_out, int out_size) {
    const float* e     = (const float*)d_in[0];
    const float* f     = (const float*)d_in[1];
    const int*   rowsG = (const int*)d_in[2];
    const int*   colsG = (const int*)d_in[3];
    const float* valsG = (const float*)d_in[4];
    const int*   rowsB = (const int*)d_in[5];
    const int*   colsB = (const int*)d_in[6];
    const float* valsB = (const float*)d_in[7];
    const int*   rows1 = (const int*)d_in[8];
    const int*   cols1 = (const int*)d_in[9];
    const float* vals1 = (const float*)d_in[10];
    const int*   rows2 = (const int*)d_in[11];
    const int*   cols2 = (const int*)d_in[12];
    const float* vals2 = (const float*)d_in[13];
    const float* G_diag = (const float*)d_in[14];
    const float* B_diag = (const float*)d_in[15];
    const float* Pd    = (const float*)d_in[16];
    const float* Qd    = (const float*)d_in[17];
    const float* W_v1  = (const float*)d_in[18];
    const float* b_v1  = (const float*)d_in[19];
    const float* W_v2  = (const float*)d_in[20];
    const float* b_v2  = (const float*)d_in[21];
    const float* w_ae  = (const float*)d_in[22];
    const float* b_ae  = (const float*)d_in[23];
    const float* w_af  = (const float*)d_in[24];
    const float* b_af  = (const float*)d_in[25];
    float* out = (float*)d_out;

    const int spmm_smem = NODES * 32 * (int)sizeof(float2);   // 169216

    cudaFuncSetAttribute(spmm_staged_kernel, cudaFuncAttributeMaxDynamicSharedMemorySize, spmm_smem);
    cudaFuncSetAttribute(gemm_mma_kernel, cudaFuncAttributeMaxDynamicSharedMemorySize, GM_SMEM);

    build_csr_kernel<<<513, 1024>>>(rowsG, colsG, valsG,
                                    rowsB, colsB, valsB,
                                    rows1, cols1, vals1,
                                    rows2, cols2, vals2,
                                    W_v1, W_v2);

    spmm_staged_kernel<<<NGRAPH * 2, 1024, spmm_smem>>>(e, f, Pd, Qd, G_diag, B_diag, w_ae, w_af);

    dim3 ggrid(NTOT / 128, 2);
    gemm_mma_kernel<<<ggrid, 256, GM_SMEM>>>(e, f, b_v1, b_v2, b_ae, b_af, out);
}